// round 15
// baseline (speedup 1.0000x reference)
#include <cuda_runtime.h>
#include <cuda_bf16.h>
#include <math_constants.h>
#include <cstdint>

#define Bn 2
#define Tn 2048
#define DMn 1024
#define Hn 16
#define DKn 64
#define DVn 64
#define BTn (Bn * Tn)

// ===========================================================================
// Scratch (allocation-free rule: __device__ globals). All "h/l" arrays hold
// packed bf16x2 pairs: hi = bf16(even,odd), lo = residual(even,odd).
// ===========================================================================
__device__ uint32_t g_xh[3 * BTn * 512];          // x k-pairs (adjacent cols)
__device__ uint32_t g_xl[3 * BTn * 512];
__device__ uint32_t g_wh[3 * Hn * 512 * 64];      // w_{q,k,v} pairs along DM
__device__ uint32_t g_wl[3 * Hn * 512 * 64];
__device__ uint32_t g_woh[512 * 1024];            // w_o pairs along H*DV
__device__ uint32_t g_wol[512 * 1024];
__device__ uint32_t g_Qh[Bn * Hn * Tn * 32];      // Q dk-pairs
__device__ uint32_t g_Ql[Bn * Hn * Tn * 32];
__device__ uint32_t g_Kh[Bn * Hn * Tn * 32];      // K dk-pairs
__device__ uint32_t g_Kl[Bn * Hn * Tn * 32];
__device__ float    g_V [Bn * Hn * Tn * DVn];     // V fp32 (pre-repack)
__device__ uint32_t g_Vh[Bn * Hn * (Tn / 2) * 64];// V key-pairs
__device__ uint32_t g_Vl[Bn * Hn * (Tn / 2) * 64];
__device__ uint32_t g_ctxh[BTn * 512];            // ctx k-pairs
__device__ uint32_t g_ctxl[BTn * 512];

// ===========================================================================
// bf16 helpers
// ===========================================================================
__device__ __forceinline__ uint32_t pack_bf16(float e, float o) {
    __nv_bfloat162 t = __floats2bfloat162_rn(e, o);
    return *(uint32_t*)&t;
}
__device__ __forceinline__ void bf16_split2(float e, float o,
                                            uint32_t& hi, uint32_t& lo) {
    float eh = __bfloat162float(__float2bfloat16_rn(e));
    float oh = __bfloat162float(__float2bfloat16_rn(o));
    hi = pack_bf16(eh, oh);
    lo = pack_bf16(e - eh, o - oh);
}
// D(16x8) += A(16x16 row, bf16x2) * B(16x8 col, bf16x2)
__device__ __forceinline__ void mma16(float* d, const uint32_t* a, const uint32_t* b) {
    asm volatile(
        "mma.sync.aligned.m16n8k16.row.col.f32.bf16.bf16.f32 "
        "{%0,%1,%2,%3}, {%4,%5,%6,%7}, {%8,%9}, {%0,%1,%2,%3};"
        : "+f"(d[0]), "+f"(d[1]), "+f"(d[2]), "+f"(d[3])
        : "r"(a[0]), "r"(a[1]), "r"(a[2]), "r"(a[3]), "r"(b[0]), "r"(b[1]));
}

// ===========================================================================
// Pre-split passes
// ===========================================================================
// x: pairs along contiguous (column) dim. One thread = one float4 (2 pairs).
__global__ __launch_bounds__(256) void split_x_kernel(
    const float* __restrict__ xq, const float* __restrict__ xk,
    const float* __restrict__ xv)
{
    const int which = blockIdx.z;
    const float* src = which == 0 ? xq : (which == 1 ? xk : xv);
    uint32_t* dh = g_xh + (size_t)which * BTn * 512;
    uint32_t* dl = g_xl + (size_t)which * BTn * 512;
    int i = blockIdx.x * 256 + threadIdx.x;       // < BTn*DMn/4 = 1048576
    float4 v = ((const float4*)src)[i];
    uint32_t h0, l0, h1, l1;
    bf16_split2(v.x, v.y, h0, l0);
    bf16_split2(v.z, v.w, h1, l1);
    *(uint2*)(dh + 2 * (size_t)i) = make_uint2(h0, h1);
    *(uint2*)(dl + 2 * (size_t)i) = make_uint2(l0, l1);
}
// w_{q,k,v}: pairs along DM (row stride 64). idx = p*64 + c.
__global__ __launch_bounds__(256) void split_w_kernel(
    const float* __restrict__ wq, const float* __restrict__ wk,
    const float* __restrict__ wv)
{
    const int which = blockIdx.z;
    const float* src = which == 0 ? wq : (which == 1 ? wk : wv);
    uint32_t* dh = g_wh + (size_t)which * Hn * 512 * 64;
    uint32_t* dl = g_wl + (size_t)which * Hn * 512 * 64;
    int idx = blockIdx.x * 256 + threadIdx.x;     // < 524288
    int p = idx >> 6, c = idx & 63;
    float a = src[(size_t)(2 * p) * 64 + c];
    float b = src[(size_t)(2 * p + 1) * 64 + c];
    uint32_t h, l; bf16_split2(a, b, h, l);
    dh[idx] = h; dl[idx] = l;
}
// w_o: pairs along first dim (row stride 1024).
__global__ __launch_bounds__(256) void split_wo_kernel(const float* __restrict__ wo)
{
    int idx = blockIdx.x * 256 + threadIdx.x;     // < 524288
    int p = idx >> 10, c = idx & 1023;
    float a = wo[(size_t)(2 * p) * 1024 + c];
    float b = wo[(size_t)(2 * p + 1) * 1024 + c];
    uint32_t h, l; bf16_split2(a, b, h, l);
    g_woh[idx] = h; g_wol[idx] = l;
}
// V: key-pairs (row stride 64 over flattened B*H*T rows).
__global__ __launch_bounds__(256) void split_v_kernel()
{
    int idx = blockIdx.x * 256 + threadIdx.x;     // < 2097152
    int p = idx >> 6, c = idx & 63;
    float a = g_V[(size_t)(2 * p) * 64 + c];
    float b = g_V[(size_t)(2 * p + 1) * 64 + c];
    uint32_t h, l; bf16_split2(a, b, h, l);
    g_Vh[idx] = h; g_Vl[idx] = l;
}

// ===========================================================================
// 3xBF16 128x64 GEMM body on PRE-SPLIT operands (512 k-pairs, 16/step),
// 256 threads = 8 warps (4m x 2n). Pure LDG->STS->LDS->MMA, no cvt.
// ===========================================================================
#define ASTu 20   // A stride in u32 (16 k-pairs + pad)
#define BSTu 72   // B stride in u32 (64 cols + pad)
#define GS_AH 0
#define GS_AL (128 * ASTu)
#define GS_BH (2 * 128 * ASTu)
#define GS_BL (2 * 128 * ASTu + 16 * BSTu)
#define GS_TOT (2 * 128 * ASTu + 2 * 16 * BSTu)   // 7424 u32 = 29696 B

__device__ __forceinline__ void gemm_body3(
    const uint32_t* __restrict__ Agh, const uint32_t* __restrict__ Agl,
    const uint32_t* __restrict__ Bgh, const uint32_t* __restrict__ Bgl,
    int ldb, float acc[2][4][4], uint32_t* gs)
{
    uint32_t* Ah = gs + GS_AH;
    uint32_t* Al = gs + GS_AL;
    uint32_t* Bh = gs + GS_BH;
    uint32_t* Bl = gs + GS_BL;

    const int tid  = threadIdx.x;
    const int lane = tid & 31;
    const int wid  = tid >> 5;
    const int gid  = lane >> 2;
    const int tig  = lane & 3;
    const int wm   = (wid >> 1) * 32;
    const int wn   = (wid & 1) * 32;
    const int bkp  = tid >> 4;          // B pair-row 0..15
    const int bc   = (tid & 15) * 4;    // B col

    for (int k0p = 0; k0p < 512; k0p += 16) {
        // A tile 128 rows x 16 pairs (uint4 = 4 pairs)
        #pragma unroll
        for (int i = 0; i < 2; i++) {
            int lin = tid + i * 256;
            int r = lin >> 2, p = (lin & 3) * 4;
            *(uint4*)(Ah + r * ASTu + p) =
                *(const uint4*)(Agh + (size_t)r * 512 + k0p + p);
            *(uint4*)(Al + r * ASTu + p) =
                *(const uint4*)(Agl + (size_t)r * 512 + k0p + p);
        }
        // B tile 16 pair-rows x 64 cols
        *(uint4*)(Bh + bkp * BSTu + bc) =
            *(const uint4*)(Bgh + (size_t)(k0p + bkp) * ldb + bc);
        *(uint4*)(Bl + bkp * BSTu + bc) =
            *(const uint4*)(Bgl + (size_t)(k0p + bkp) * ldb + bc);
        __syncthreads();

        #pragma unroll
        for (int kk = 0; kk < 2; kk++) {
            uint32_t ah[2][4], al[2][4];
            #pragma unroll
            for (int m = 0; m < 2; m++) {
                int r0 = (wm + m * 16 + gid) * ASTu + kk * 8 + tig;
                int r1 = (wm + m * 16 + 8 + gid) * ASTu + kk * 8 + tig;
                ah[m][0] = Ah[r0]; ah[m][1] = Ah[r1];
                ah[m][2] = Ah[r0 + 4]; ah[m][3] = Ah[r1 + 4];
                al[m][0] = Al[r0]; al[m][1] = Al[r1];
                al[m][2] = Al[r0 + 4]; al[m][3] = Al[r1 + 4];
            }
            uint32_t bh[4][2], bl[4][2];
            #pragma unroll
            for (int n = 0; n < 4; n++) {
                int b0 = (kk * 8 + tig) * BSTu + wn + n * 8 + gid;
                int b1 = (kk * 8 + 4 + tig) * BSTu + wn + n * 8 + gid;
                bh[n][0] = Bh[b0]; bh[n][1] = Bh[b1];
                bl[n][0] = Bl[b0]; bl[n][1] = Bl[b1];
            }
            #pragma unroll
            for (int n = 0; n < 4; n++)
                #pragma unroll
                for (int m = 0; m < 2; m++) mma16(acc[m][n], al[m], bh[n]);
            #pragma unroll
            for (int n = 0; n < 4; n++)
                #pragma unroll
                for (int m = 0; m < 2; m++) mma16(acc[m][n], ah[m], bl[n]);
            #pragma unroll
            for (int n = 0; n < 4; n++)
                #pragma unroll
                for (int m = 0; m < 2; m++) mma16(acc[m][n], ah[m], bh[n]);
        }
        __syncthreads();
    }
}

// ---------------------------------------------------------------------------
// QKV projection: grid (BT/128, H, 3), block 256. Q/K written pre-split.
// ---------------------------------------------------------------------------
__global__ __launch_bounds__(256, 2) void proj_kernel()
{
    extern __shared__ __align__(16) uint32_t gs[];

    const int which = blockIdx.z;
    const int h     = blockIdx.y;
    const int row0  = blockIdx.x * 128;

    const uint32_t* Agh = g_xh + (size_t)which * BTn * 512 + (size_t)row0 * 512;
    const uint32_t* Agl = g_xl + (size_t)which * BTn * 512 + (size_t)row0 * 512;
    const uint32_t* Bgh = g_wh + ((size_t)which * Hn + h) * 512 * 64;
    const uint32_t* Bgl = g_wl + ((size_t)which * Hn + h) * 512 * 64;

    float acc[2][4][4] = {};
    gemm_body3(Agh, Agl, Bgh, Bgl, 64, acc, gs);

    const int lane = threadIdx.x & 31;
    const int wid  = threadIdx.x >> 5;
    const int gid  = lane >> 2;
    const int tig  = lane & 3;
    const int wm   = (wid >> 1) * 32;
    const int wn   = (wid & 1) * 32;

    const int b = row0 >> 11;       // 128-row blocks never straddle batch
    #pragma unroll
    for (int m = 0; m < 2; m++) {
        int r = row0 + wm + m * 16 + gid;
        int t = r & 2047;
        size_t bh = (size_t)(b * Hn + h);
        if (which < 2) {
            uint32_t* oh = (which == 0 ? g_Qh : g_Kh);
            uint32_t* ol = (which == 0 ? g_Ql : g_Kl);
            size_t base0 = (bh * Tn + t) * 32;
            size_t base1 = base0 + 8 * 32;
            #pragma unroll
            for (int n = 0; n < 4; n++) {
                int pi = wn / 2 + n * 4 + tig;
                uint32_t hh, ll;
                bf16_split2(acc[m][n][0], acc[m][n][1], hh, ll);
                oh[base0 + pi] = hh; ol[base0 + pi] = ll;
                bf16_split2(acc[m][n][2], acc[m][n][3], hh, ll);
                oh[base1 + pi] = hh; ol[base1 + pi] = ll;
            }
        } else {
            size_t base0 = (bh * Tn + t) * DVn;
            size_t base1 = base0 + 8 * DVn;
            #pragma unroll
            for (int n = 0; n < 4; n++) {
                int c = wn + n * 8 + tig * 2;
                *(float2*)(g_V + base0 + c) = make_float2(acc[m][n][0], acc[m][n][1]);
                *(float2*)(g_V + base1 + c) = make_float2(acc[m][n][2], acc[m][n][3]);
            }
        }
    }
}

// ---------------------------------------------------------------------------
// Output projection: grid (BT/128, DM/64), block 256. Inputs pre-split.
// ---------------------------------------------------------------------------
__global__ __launch_bounds__(256, 2) void out_proj_kernel(
    const float* __restrict__ bo, float* __restrict__ out)
{
    extern __shared__ __align__(16) uint32_t gs[];

    const int row0 = blockIdx.x * 128;
    const int col0 = blockIdx.y * 64;

    float acc[2][4][4] = {};
    gemm_body3(g_ctxh + (size_t)row0 * 512, g_ctxl + (size_t)row0 * 512,
               g_woh + col0, g_wol + col0, 1024, acc, gs);

    const int lane = threadIdx.x & 31;
    const int wid  = threadIdx.x >> 5;
    const int gid  = lane >> 2;
    const int tig  = lane & 3;
    const int wm   = (wid >> 1) * 32;
    const int wn   = (wid & 1) * 32;

    #pragma unroll
    for (int m = 0; m < 2; m++) {
        int r = row0 + wm + m * 16 + gid;
        #pragma unroll
        for (int n = 0; n < 4; n++) {
            int c = col0 + wn + n * 8 + tig * 2;
            float2 bb = *(const float2*)(bo + c);
            *(float2*)(out + (size_t)r * DMn + c) =
                make_float2(acc[m][n][0] + bb.x, acc[m][n][1] + bb.y);
            *(float2*)(out + (size_t)(r + 8) * DMn + c) =
                make_float2(acc[m][n][2] + bb.x, acc[m][n][3] + bb.y);
        }
    }
}

// ---------------------------------------------------------------------------
// Flash attention on pre-split Q/K/V. QK = 3xBF16, PV = 3-term bf16 from regs.
// grid (T/64, H, B), block 128 (4 warps); warp owns 16 query rows.
// ---------------------------------------------------------------------------
#define KSTu 36
#define VSTu 72
#define FS_KH 0
#define FS_KL (128 * KSTu)
#define FS_VH (2 * 128 * KSTu)
#define FS_VL (FS_VH + 64 * VSTu)
#define FS_M  (FS_VL + 64 * VSTu)
#define FS_TOT (FS_M + 128)               // 18560 u32 = 74240 B

__global__ __launch_bounds__(128, 3) void flash_kernel(
    const float* __restrict__ mask)
{
    extern __shared__ __align__(16) uint32_t fsu[];
    uint32_t* Kh = fsu + FS_KH;
    uint32_t* Kl = fsu + FS_KL;
    uint32_t* Vh = fsu + FS_VH;
    uint32_t* Vl = fsu + FS_VL;
    float*    Ms = (float*)(fsu + FS_M);

    const int tid  = threadIdx.x;
    const int lane = tid & 31;
    const int wid  = tid >> 5;
    const int gid  = lane >> 2;
    const int tig  = lane & 3;

    const int b  = blockIdx.z;
    const int h  = blockIdx.y;
    const int q0 = blockIdx.x * 64;
    const size_t bh = (size_t)(b * Hn + h);
    const int qr = q0 + wid * 16;

    // Q fragments: direct u32 loads from pre-split arrays
    const uint32_t* Qhp = g_Qh + (bh * Tn + qr) * 32;
    const uint32_t* Qlp = g_Ql + (bh * Tn + qr) * 32;
    uint32_t qh[4][4], ql[4][4];
    #pragma unroll
    for (int kk = 0; kk < 4; kk++) {
        qh[kk][0] = Qhp[gid * 32 + kk * 8 + tig];
        qh[kk][1] = Qhp[(gid + 8) * 32 + kk * 8 + tig];
        qh[kk][2] = Qhp[gid * 32 + kk * 8 + 4 + tig];
        qh[kk][3] = Qhp[(gid + 8) * 32 + kk * 8 + 4 + tig];
        ql[kk][0] = Qlp[gid * 32 + kk * 8 + tig];
        ql[kk][1] = Qlp[(gid + 8) * 32 + kk * 8 + tig];
        ql[kk][2] = Qlp[gid * 32 + kk * 8 + 4 + tig];
        ql[kk][3] = Qlp[(gid + 8) * 32 + kk * 8 + 4 + tig];
    }

    float o[8][4];
    #pragma unroll
    for (int n = 0; n < 8; n++)
        #pragma unroll
        for (int c = 0; c < 4; c++) o[n][c] = 0.0f;

    float m0 = -CUDART_INF_F, m1 = -CUDART_INF_F;
    float l0 = 0.0f, l1 = 0.0f;
    const float inv_dk = 1.0f / 64.0f;

    for (int kt0 = 0; kt0 < Tn; kt0 += 128) {
        __syncthreads();   // K/V tiles free for reuse
        // K tile 128 rows x 32 pairs (uint4 = 4 pairs)
        const uint32_t* Kgh = g_Kh + (bh * Tn + kt0) * 32;
        const uint32_t* Kgl = g_Kl + (bh * Tn + kt0) * 32;
        #pragma unroll
        for (int i = 0; i < 8; i++) {
            int lin = tid + i * 128;
            int r = lin >> 3, cq = (lin & 7) * 4;
            *(uint4*)(Kh + r * KSTu + cq) = *(const uint4*)(Kgh + (size_t)r * 32 + cq);
            *(uint4*)(Kl + r * KSTu + cq) = *(const uint4*)(Kgl + (size_t)r * 32 + cq);
        }
        // V tile 64 pair-rows x 64 cols
        const uint32_t* Vgh = g_Vh + (bh * (Tn / 2) + kt0 / 2) * 64;
        const uint32_t* Vgl = g_Vl + (bh * (Tn / 2) + kt0 / 2) * 64;
        #pragma unroll
        for (int i = 0; i < 8; i++) {
            int lin = tid + i * 128;
            int p = lin >> 4, c = (lin & 15) * 4;
            *(uint4*)(Vh + p * VSTu + c) = *(const uint4*)(Vgh + (size_t)p * 64 + c);
            *(uint4*)(Vl + p * VSTu + c) = *(const uint4*)(Vgl + (size_t)p * 64 + c);
        }
        Ms[tid] = mask[b * Tn + kt0 + tid];
        __syncthreads();

        #pragma unroll
        for (int half = 0; half < 2; half++) {
            // ---- S = Q @ K^T over 64-key subtile : 3xBF16, term-outer ----
            float sc[8][4];
            #pragma unroll
            for (int n = 0; n < 8; n++)
                #pragma unroll
                for (int c = 0; c < 4; c++) sc[n][c] = 0.0f;
            #pragma unroll
            for (int kk = 0; kk < 4; kk++) {
                uint32_t kbh[8][2], kbl[8][2];
                #pragma unroll
                for (int n = 0; n < 8; n++) {
                    int base = ((half * 8 + n) * 8 + gid) * KSTu + kk * 8 + tig;
                    kbh[n][0] = Kh[base]; kbh[n][1] = Kh[base + 4];
                    kbl[n][0] = Kl[base]; kbl[n][1] = Kl[base + 4];
                }
                #pragma unroll
                for (int n = 0; n < 8; n++) mma16(sc[n], ql[kk], kbh[n]);
                #pragma unroll
                for (int n = 0; n < 8; n++) mma16(sc[n], qh[kk], kbl[n]);
                #pragma unroll
                for (int n = 0; n < 8; n++) mma16(sc[n], qh[kk], kbh[n]);
            }

            // ---- masked scale + faithful zero->-inf quirk + row max ----
            float mx0 = -CUDART_INF_F, mx1 = -CUDART_INF_F;
            #pragma unroll
            for (int n = 0; n < 8; n++) {
                float mk0 = Ms[half * 64 + n * 8 + tig * 2];
                float mk1 = Ms[half * 64 + n * 8 + tig * 2 + 1];
                float s0 = sc[n][0] * inv_dk * mk0; s0 = (s0 == 0.0f) ? -CUDART_INF_F : s0;
                float s1 = sc[n][1] * inv_dk * mk1; s1 = (s1 == 0.0f) ? -CUDART_INF_F : s1;
                float s2 = sc[n][2] * inv_dk * mk0; s2 = (s2 == 0.0f) ? -CUDART_INF_F : s2;
                float s3 = sc[n][3] * inv_dk * mk1; s3 = (s3 == 0.0f) ? -CUDART_INF_F : s3;
                sc[n][0] = s0; sc[n][1] = s1; sc[n][2] = s2; sc[n][3] = s3;
                mx0 = fmaxf(mx0, fmaxf(s0, s1));
                mx1 = fmaxf(mx1, fmaxf(s2, s3));
            }
            mx0 = fmaxf(mx0, __shfl_xor_sync(0xffffffffu, mx0, 1));
            mx0 = fmaxf(mx0, __shfl_xor_sync(0xffffffffu, mx0, 2));
            mx1 = fmaxf(mx1, __shfl_xor_sync(0xffffffffu, mx1, 1));
            mx1 = fmaxf(mx1, __shfl_xor_sync(0xffffffffu, mx1, 2));

            float mn0 = fmaxf(m0, mx0);
            float mn1 = fmaxf(m1, mx1);
            float scale0 = (m0 >= mn0) ? 1.0f : __expf(m0 - mn0);
            float scale1 = (m1 >= mn1) ? 1.0f : __expf(m1 - mn1);

            // ---- exp (in place) + l accumulate ----
            float ls0 = 0.0f, ls1 = 0.0f;
            #pragma unroll
            for (int n = 0; n < 8; n++) {
                float p0 = __expf(sc[n][0] - mn0);
                float p1 = __expf(sc[n][1] - mn0);
                float p2 = __expf(sc[n][2] - mn1);
                float p3 = __expf(sc[n][3] - mn1);
                ls0 += p0 + p1;
                ls1 += p2 + p3;
                sc[n][0] = p0; sc[n][1] = p1; sc[n][2] = p2; sc[n][3] = p3;
            }
            l0 = l0 * scale0 + ls0;
            l1 = l1 * scale1 + ls1;
            m0 = mn0; m1 = mn1;

            // ---- rescale O, then O += P @ V (3-term bf16, term-outer) ----
            #pragma unroll
            for (int n = 0; n < 8; n++) {
                o[n][0] *= scale0; o[n][1] *= scale0;
                o[n][2] *= scale1; o[n][3] *= scale1;
            }
            #pragma unroll
            for (int kk = 0; kk < 4; kk++) {
                uint32_t pah[4], pal[4];
                bf16_split2(sc[2*kk][0],   sc[2*kk][1],   pah[0], pal[0]);
                bf16_split2(sc[2*kk][2],   sc[2*kk][3],   pah[1], pal[1]);
                bf16_split2(sc[2*kk+1][0], sc[2*kk+1][1], pah[2], pal[2]);
                bf16_split2(sc[2*kk+1][2], sc[2*kk+1][3], pah[3], pal[3]);
                uint32_t vbh[8][2], vbl[8][2];
                #pragma unroll
                for (int n = 0; n < 8; n++) {
                    int v0 = (half * 32 + kk * 8 + tig) * VSTu + n * 8 + gid;
                    int v1 = (half * 32 + kk * 8 + 4 + tig) * VSTu + n * 8 + gid;
                    vbh[n][0] = Vh[v0]; vbh[n][1] = Vh[v1];
                    vbl[n][0] = Vl[v0]; vbl[n][1] = Vl[v1];
                }
                #pragma unroll
                for (int n = 0; n < 8; n++) mma16(o[n], pal, vbh[n]);
                #pragma unroll
                for (int n = 0; n < 8; n++) mma16(o[n], pah, vbl[n]);
                #pragma unroll
                for (int n = 0; n < 8; n++) mma16(o[n], pah, vbh[n]);
            }
        }
    }

    // ---- finalize: row sums, normalize, write ctx PRE-SPLIT ----
    l0 += __shfl_xor_sync(0xffffffffu, l0, 1);
    l0 += __shfl_xor_sync(0xffffffffu, l0, 2);
    l1 += __shfl_xor_sync(0xffffffffu, l1, 1);
    l1 += __shfl_xor_sync(0xffffffffu, l1, 2);
    const float i0 = 1.0f / l0;
    const float i1 = 1.0f / l1;

    size_t base0 = (size_t)(b * Tn + qr + gid) * 512 + h * 32;
    size_t base1 = base0 + 8 * 512;
    #pragma unroll
    for (int n = 0; n < 8; n++) {
        int pi = n * 4 + tig;
        uint32_t hh, ll;
        bf16_split2(o[n][0] * i0, o[n][1] * i0, hh, ll);
        g_ctxh[base0 + pi] = hh; g_ctxl[base0 + pi] = ll;
        bf16_split2(o[n][2] * i1, o[n][3] * i1, hh, ll);
        g_ctxh[base1 + pi] = hh; g_ctxl[base1 + pi] = ll;
    }
}

// ---------------------------------------------------------------------------
extern "C" void kernel_launch(void* const* d_in, const int* in_sizes, int n_in,
                              void* d_out, int out_size)
{
    const float* xq   = (const float*)d_in[0];
    const float* xk   = (const float*)d_in[1];
    const float* xv   = (const float*)d_in[2];
    const float* mask = (const float*)d_in[3];
    const float* w_q  = (const float*)d_in[4];
    const float* w_k  = (const float*)d_in[5];
    const float* w_v  = (const float*)d_in[6];
    const float* w_o  = (const float*)d_in[7];
    const float* b_o  = (const float*)d_in[8];
    float* out        = (float*)d_out;

    const int gemm_smem  = GS_TOT * (int)sizeof(uint32_t);   // 29696 B
    const int flash_smem = FS_TOT * (int)sizeof(uint32_t);   // 74240 B
    cudaFuncSetAttribute(proj_kernel,
                         cudaFuncAttributeMaxDynamicSharedMemorySize, gemm_smem);
    cudaFuncSetAttribute(out_proj_kernel,
                         cudaFuncAttributeMaxDynamicSharedMemorySize, gemm_smem);
    cudaFuncSetAttribute(flash_kernel,
                         cudaFuncAttributeMaxDynamicSharedMemorySize, flash_smem);

    // pre-split passes
    split_x_kernel<<<dim3(BTn * DMn / 4 / 256, 1, 3), 256>>>(xq, xk, xv);
    split_w_kernel<<<dim3(Hn * 512 * 64 / 256, 1, 3), 256>>>(w_q, w_k, w_v);
    split_wo_kernel<<<512 * 1024 / 256, 256>>>(w_o);

    dim3 projGrid(BTn / 128, Hn, 3);
    proj_kernel<<<projGrid, 256, gemm_smem>>>();

    split_v_kernel<<<(Bn * Hn * Tn / 2) * 64 / 256, 256>>>();

    dim3 flashGrid(Tn / 64, Hn, Bn);
    flash_kernel<<<flashGrid, 128, flash_smem>>>(mask);

    dim3 outGrid(BTn / 128, DMn / 64);
    out_proj_kernel<<<outGrid, 256, gemm_smem>>>(b_o, out);
}

// round 16
// speedup vs baseline: 1.1488x; 1.1488x over previous
#include <cuda_runtime.h>
#include <cuda_bf16.h>
#include <math_constants.h>
#include <cstdint>

#define Bn 2
#define Tn 2048
#define DMn 1024
#define Hn 16
#define DKn 64
#define DVn 64
#define BTn (Bn * Tn)

// ===========================================================================
// Scratch (allocation-free rule: __device__ globals). All "h/l" arrays hold
// packed bf16x2 pairs: hi = bf16(even,odd), lo = residual(even,odd).
// ===========================================================================
__device__ uint32_t g_xh[3 * BTn * 512];          // x k-pairs (adjacent cols)
__device__ uint32_t g_xl[3 * BTn * 512];
__device__ uint32_t g_wh[3 * Hn * 512 * 64];      // w_{q,k,v} pairs along DM
__device__ uint32_t g_wl[3 * Hn * 512 * 64];
__device__ uint32_t g_woh[512 * 1024];            // w_o pairs along H*DV
__device__ uint32_t g_wol[512 * 1024];
__device__ uint32_t g_Qh[Bn * Hn * Tn * 32];      // Q dk-pairs
__device__ uint32_t g_Ql[Bn * Hn * Tn * 32];
__device__ uint32_t g_Kh[Bn * Hn * Tn * 32];      // K dk-pairs
__device__ uint32_t g_Kl[Bn * Hn * Tn * 32];
__device__ float    g_V [Bn * Hn * Tn * DVn];     // V fp32 (pre-repack)
__device__ uint32_t g_Vh[Bn * Hn * (Tn / 2) * 64];// V key-pairs
__device__ uint32_t g_Vl[Bn * Hn * (Tn / 2) * 64];
__device__ uint32_t g_ctxh[BTn * 512];            // ctx k-pairs
__device__ uint32_t g_ctxl[BTn * 512];

// ===========================================================================
// bf16 / cp.async helpers (base PTX, compute_103-safe)
// ===========================================================================
__device__ __forceinline__ uint32_t pack_bf16(float e, float o) {
    __nv_bfloat162 t = __floats2bfloat162_rn(e, o);
    return *(uint32_t*)&t;
}
__device__ __forceinline__ void bf16_split2(float e, float o,
                                            uint32_t& hi, uint32_t& lo) {
    float eh = __bfloat162float(__float2bfloat16_rn(e));
    float oh = __bfloat162float(__float2bfloat16_rn(o));
    hi = pack_bf16(eh, oh);
    lo = pack_bf16(e - eh, o - oh);
}
__device__ __forceinline__ void mma16(float* d, const uint32_t* a, const uint32_t* b) {
    asm volatile(
        "mma.sync.aligned.m16n8k16.row.col.f32.bf16.bf16.f32 "
        "{%0,%1,%2,%3}, {%4,%5,%6,%7}, {%8,%9}, {%0,%1,%2,%3};"
        : "+f"(d[0]), "+f"(d[1]), "+f"(d[2]), "+f"(d[3])
        : "r"(a[0]), "r"(a[1]), "r"(a[2]), "r"(a[3]), "r"(b[0]), "r"(b[1]));
}
__device__ __forceinline__ void cp16(uint32_t dst_smem, const void* src) {
    asm volatile("cp.async.cg.shared.global [%0], [%1], 16;"
                 :: "r"(dst_smem), "l"(src));
}
#define CP_COMMIT() asm volatile("cp.async.commit_group;" ::: "memory")
#define CP_WAIT0()  asm volatile("cp.async.wait_group 0;" ::: "memory")
#define CP_WAIT1()  asm volatile("cp.async.wait_group 1;" ::: "memory")

// ===========================================================================
// Pre-split passes
// ===========================================================================
__global__ __launch_bounds__(256) void split_x_kernel(
    const float* __restrict__ xq, const float* __restrict__ xk,
    const float* __restrict__ xv)
{
    const int which = blockIdx.z;
    const float* src = which == 0 ? xq : (which == 1 ? xk : xv);
    uint32_t* dh = g_xh + (size_t)which * BTn * 512;
    uint32_t* dl = g_xl + (size_t)which * BTn * 512;
    int i = blockIdx.x * 256 + threadIdx.x;       // < BTn*DMn/4 = 1048576
    float4 v = ((const float4*)src)[i];
    uint32_t h0, l0, h1, l1;
    bf16_split2(v.x, v.y, h0, l0);
    bf16_split2(v.z, v.w, h1, l1);
    *(uint2*)(dh + 2 * (size_t)i) = make_uint2(h0, h1);
    *(uint2*)(dl + 2 * (size_t)i) = make_uint2(l0, l1);
}
__global__ __launch_bounds__(256) void split_w_kernel(
    const float* __restrict__ wq, const float* __restrict__ wk,
    const float* __restrict__ wv)
{
    const int which = blockIdx.z;
    const float* src = which == 0 ? wq : (which == 1 ? wk : wv);
    uint32_t* dh = g_wh + (size_t)which * Hn * 512 * 64;
    uint32_t* dl = g_wl + (size_t)which * Hn * 512 * 64;
    int idx = blockIdx.x * 256 + threadIdx.x;     // < 524288
    int p = idx >> 6, c = idx & 63;
    float a = src[(size_t)(2 * p) * 64 + c];
    float b = src[(size_t)(2 * p + 1) * 64 + c];
    uint32_t h, l; bf16_split2(a, b, h, l);
    dh[idx] = h; dl[idx] = l;
}
__global__ __launch_bounds__(256) void split_wo_kernel(const float* __restrict__ wo)
{
    int idx = blockIdx.x * 256 + threadIdx.x;     // < 524288
    int p = idx >> 10, c = idx & 1023;
    float a = wo[(size_t)(2 * p) * 1024 + c];
    float b = wo[(size_t)(2 * p + 1) * 1024 + c];
    uint32_t h, l; bf16_split2(a, b, h, l);
    g_woh[idx] = h; g_wol[idx] = l;
}
__global__ __launch_bounds__(256) void split_v_kernel()
{
    int idx = blockIdx.x * 256 + threadIdx.x;     // < 2097152
    int p = idx >> 6, c = idx & 63;
    float a = g_V[(size_t)(2 * p) * 64 + c];
    float b = g_V[(size_t)(2 * p + 1) * 64 + c];
    uint32_t h, l; bf16_split2(a, b, h, l);
    g_Vh[idx] = h; g_Vl[idx] = l;
}

// ===========================================================================
// 3xBF16 128x64 GEMM body on PRE-SPLIT operands, cp.async DOUBLE-BUFFERED.
// 256 threads = 8 warps (4m x 2n). 32 k-pair tiles of 16.
// ===========================================================================
#define ASTu 20   // A stride in u32 (16 k-pairs + pad)
#define BSTu 72   // B stride in u32 (64 cols + pad)
#define GS_AH 0
#define GS_AL (128 * ASTu)
#define GS_BH (2 * 128 * ASTu)
#define GS_BL (2 * 128 * ASTu + 16 * BSTu)
#define GS_TOT (2 * 128 * ASTu + 2 * 16 * BSTu)   // 7424 u32 per stage
#define GS_BYTES (2 * GS_TOT * 4)                 // 59392 B (two stages)

__device__ __forceinline__ void gemm_body3(
    const uint32_t* __restrict__ Agh, const uint32_t* __restrict__ Agl,
    const uint32_t* __restrict__ Bgh, const uint32_t* __restrict__ Bgl,
    int ldb, float acc[2][4][4], uint32_t* gs)
{
    const int tid  = threadIdx.x;
    const int lane = tid & 31;
    const int wid  = tid >> 5;
    const int gid  = lane >> 2;
    const int tig  = lane & 3;
    const int wm   = (wid >> 1) * 32;
    const int wn   = (wid & 1) * 32;
    const int bkp  = tid >> 4;          // B pair-row 0..15
    const int bc   = (tid & 15) * 4;    // B col

    const uint32_t gsa = (uint32_t)__cvta_generic_to_shared(gs);

    auto issue = [&](int k0p, int stage) {
        uint32_t base = gsa + (uint32_t)stage * GS_TOT * 4;
        #pragma unroll
        for (int i = 0; i < 2; i++) {
            int lin = tid + i * 256;
            int r = lin >> 2, p = (lin & 3) * 4;
            cp16(base + (GS_AH + r * ASTu + p) * 4, Agh + (size_t)r * 512 + k0p + p);
            cp16(base + (GS_AL + r * ASTu + p) * 4, Agl + (size_t)r * 512 + k0p + p);
        }
        cp16(base + (GS_BH + bkp * BSTu + bc) * 4, Bgh + (size_t)(k0p + bkp) * ldb + bc);
        cp16(base + (GS_BL + bkp * BSTu + bc) * 4, Bgl + (size_t)(k0p + bkp) * ldb + bc);
        CP_COMMIT();
    };

    issue(0, 0);

    for (int t = 0; t < 32; t++) {
        const int cur = t & 1;
        if (t < 31) { issue((t + 1) * 16, (t + 1) & 1); CP_WAIT1(); }
        else        { CP_WAIT0(); }
        __syncthreads();

        uint32_t* Ah = gs + cur * GS_TOT + GS_AH;
        uint32_t* Al = gs + cur * GS_TOT + GS_AL;
        uint32_t* Bh = gs + cur * GS_TOT + GS_BH;
        uint32_t* Bl = gs + cur * GS_TOT + GS_BL;

        #pragma unroll
        for (int kk = 0; kk < 2; kk++) {
            uint32_t ah[2][4], al[2][4];
            #pragma unroll
            for (int m = 0; m < 2; m++) {
                int r0 = (wm + m * 16 + gid) * ASTu + kk * 8 + tig;
                int r1 = (wm + m * 16 + 8 + gid) * ASTu + kk * 8 + tig;
                ah[m][0] = Ah[r0]; ah[m][1] = Ah[r1];
                ah[m][2] = Ah[r0 + 4]; ah[m][3] = Ah[r1 + 4];
                al[m][0] = Al[r0]; al[m][1] = Al[r1];
                al[m][2] = Al[r0 + 4]; al[m][3] = Al[r1 + 4];
            }
            uint32_t bh[4][2], bl[4][2];
            #pragma unroll
            for (int n = 0; n < 4; n++) {
                int b0 = (kk * 8 + tig) * BSTu + wn + n * 8 + gid;
                int b1 = (kk * 8 + 4 + tig) * BSTu + wn + n * 8 + gid;
                bh[n][0] = Bh[b0]; bh[n][1] = Bh[b1];
                bl[n][0] = Bl[b0]; bl[n][1] = Bl[b1];
            }
            #pragma unroll
            for (int n = 0; n < 4; n++)
                #pragma unroll
                for (int m = 0; m < 2; m++) mma16(acc[m][n], al[m], bh[n]);
            #pragma unroll
            for (int n = 0; n < 4; n++)
                #pragma unroll
                for (int m = 0; m < 2; m++) mma16(acc[m][n], ah[m], bl[n]);
            #pragma unroll
            for (int n = 0; n < 4; n++)
                #pragma unroll
                for (int m = 0; m < 2; m++) mma16(acc[m][n], ah[m], bh[n]);
        }
        __syncthreads();   // all warps done reading before this stage is refilled
    }
}

// ---------------------------------------------------------------------------
// QKV projection: grid (BT/128, H, 3), block 256. Q/K written pre-split.
// ---------------------------------------------------------------------------
__global__ __launch_bounds__(256, 2) void proj_kernel()
{
    extern __shared__ __align__(16) uint32_t gs[];

    const int which = blockIdx.z;
    const int h     = blockIdx.y;
    const int row0  = blockIdx.x * 128;

    const uint32_t* Agh = g_xh + (size_t)which * BTn * 512 + (size_t)row0 * 512;
    const uint32_t* Agl = g_xl + (size_t)which * BTn * 512 + (size_t)row0 * 512;
    const uint32_t* Bgh = g_wh + ((size_t)which * Hn + h) * 512 * 64;
    const uint32_t* Bgl = g_wl + ((size_t)which * Hn + h) * 512 * 64;

    float acc[2][4][4] = {};
    gemm_body3(Agh, Agl, Bgh, Bgl, 64, acc, gs);

    const int lane = threadIdx.x & 31;
    const int wid  = threadIdx.x >> 5;
    const int gid  = lane >> 2;
    const int tig  = lane & 3;
    const int wm   = (wid >> 1) * 32;
    const int wn   = (wid & 1) * 32;

    const int b = row0 >> 11;       // 128-row blocks never straddle batch
    #pragma unroll
    for (int m = 0; m < 2; m++) {
        int r = row0 + wm + m * 16 + gid;
        int t = r & 2047;
        size_t bh = (size_t)(b * Hn + h);
        if (which < 2) {
            uint32_t* oh = (which == 0 ? g_Qh : g_Kh);
            uint32_t* ol = (which == 0 ? g_Ql : g_Kl);
            size_t base0 = (bh * Tn + t) * 32;
            size_t base1 = base0 + 8 * 32;
            #pragma unroll
            for (int n = 0; n < 4; n++) {
                int pi = wn / 2 + n * 4 + tig;
                uint32_t hh, ll;
                bf16_split2(acc[m][n][0], acc[m][n][1], hh, ll);
                oh[base0 + pi] = hh; ol[base0 + pi] = ll;
                bf16_split2(acc[m][n][2], acc[m][n][3], hh, ll);
                oh[base1 + pi] = hh; ol[base1 + pi] = ll;
            }
        } else {
            size_t base0 = (bh * Tn + t) * DVn;
            size_t base1 = base0 + 8 * DVn;
            #pragma unroll
            for (int n = 0; n < 4; n++) {
                int c = wn + n * 8 + tig * 2;
                *(float2*)(g_V + base0 + c) = make_float2(acc[m][n][0], acc[m][n][1]);
                *(float2*)(g_V + base1 + c) = make_float2(acc[m][n][2], acc[m][n][3]);
            }
        }
    }
}

// ---------------------------------------------------------------------------
// Output projection: grid (BT/128, DM/64), block 256. Inputs pre-split.
// ---------------------------------------------------------------------------
__global__ __launch_bounds__(256, 2) void out_proj_kernel(
    const float* __restrict__ bo, float* __restrict__ out)
{
    extern __shared__ __align__(16) uint32_t gs[];

    const int row0 = blockIdx.x * 128;
    const int col0 = blockIdx.y * 64;

    float acc[2][4][4] = {};
    gemm_body3(g_ctxh + (size_t)row0 * 512, g_ctxl + (size_t)row0 * 512,
               g_woh + col0, g_wol + col0, 1024, acc, gs);

    const int lane = threadIdx.x & 31;
    const int wid  = threadIdx.x >> 5;
    const int gid  = lane >> 2;
    const int tig  = lane & 3;
    const int wm   = (wid >> 1) * 32;
    const int wn   = (wid & 1) * 32;

    #pragma unroll
    for (int m = 0; m < 2; m++) {
        int r = row0 + wm + m * 16 + gid;
        #pragma unroll
        for (int n = 0; n < 4; n++) {
            int c = col0 + wn + n * 8 + tig * 2;
            float2 bb = *(const float2*)(bo + c);
            *(float2*)(out + (size_t)r * DMn + c) =
                make_float2(acc[m][n][0] + bb.x, acc[m][n][1] + bb.y);
            *(float2*)(out + (size_t)(r + 8) * DMn + c) =
                make_float2(acc[m][n][2] + bb.x, acc[m][n][3] + bb.y);
        }
    }
}

// ---------------------------------------------------------------------------
// Flash attention on pre-split Q/K/V. QK = 3xBF16, PV = 3-term bf16 from regs.
// K/V tiles staged via cp.async (single stage; 3 CTAs/SM give cross-CTA overlap).
// grid (T/64, H, B), block 128 (4 warps); warp owns 16 query rows.
// ---------------------------------------------------------------------------
#define KSTu 36
#define VSTu 72
#define FS_KH 0
#define FS_KL (128 * KSTu)
#define FS_VH (2 * 128 * KSTu)
#define FS_VL (FS_VH + 64 * VSTu)
#define FS_M  (FS_VL + 64 * VSTu)
#define FS_TOT (FS_M + 128)               // 18560 u32 = 74240 B

__global__ __launch_bounds__(128, 3) void flash_kernel(
    const float* __restrict__ mask)
{
    extern __shared__ __align__(16) uint32_t fsu[];
    uint32_t* Kh = fsu + FS_KH;
    uint32_t* Kl = fsu + FS_KL;
    uint32_t* Vh = fsu + FS_VH;
    uint32_t* Vl = fsu + FS_VL;
    float*    Ms = (float*)(fsu + FS_M);
    const uint32_t fsb = (uint32_t)__cvta_generic_to_shared(fsu);

    const int tid  = threadIdx.x;
    const int lane = tid & 31;
    const int wid  = tid >> 5;
    const int gid  = lane >> 2;
    const int tig  = lane & 3;

    const int b  = blockIdx.z;
    const int h  = blockIdx.y;
    const int q0 = blockIdx.x * 64;
    const size_t bh = (size_t)(b * Hn + h);
    const int qr = q0 + wid * 16;

    // Q fragments: direct u32 loads from pre-split arrays
    const uint32_t* Qhp = g_Qh + (bh * Tn + qr) * 32;
    const uint32_t* Qlp = g_Ql + (bh * Tn + qr) * 32;
    uint32_t qh[4][4], ql[4][4];
    #pragma unroll
    for (int kk = 0; kk < 4; kk++) {
        qh[kk][0] = Qhp[gid * 32 + kk * 8 + tig];
        qh[kk][1] = Qhp[(gid + 8) * 32 + kk * 8 + tig];
        qh[kk][2] = Qhp[gid * 32 + kk * 8 + 4 + tig];
        qh[kk][3] = Qhp[(gid + 8) * 32 + kk * 8 + 4 + tig];
        ql[kk][0] = Qlp[gid * 32 + kk * 8 + tig];
        ql[kk][1] = Qlp[(gid + 8) * 32 + kk * 8 + tig];
        ql[kk][2] = Qlp[gid * 32 + kk * 8 + 4 + tig];
        ql[kk][3] = Qlp[(gid + 8) * 32 + kk * 8 + 4 + tig];
    }

    float o[8][4];
    #pragma unroll
    for (int n = 0; n < 8; n++)
        #pragma unroll
        for (int c = 0; c < 4; c++) o[n][c] = 0.0f;

    float m0 = -CUDART_INF_F, m1 = -CUDART_INF_F;
    float l0 = 0.0f, l1 = 0.0f;
    const float inv_dk = 1.0f / 64.0f;

    for (int kt0 = 0; kt0 < Tn; kt0 += 128) {
        __syncthreads();   // K/V tiles free for reuse
        // K tile 128 rows x 32 pairs via cp.async
        const uint32_t* Kgh = g_Kh + (bh * Tn + kt0) * 32;
        const uint32_t* Kgl = g_Kl + (bh * Tn + kt0) * 32;
        #pragma unroll
        for (int i = 0; i < 8; i++) {
            int lin = tid + i * 128;
            int r = lin >> 3, cq = (lin & 7) * 4;
            cp16(fsb + (FS_KH + r * KSTu + cq) * 4, Kgh + (size_t)r * 32 + cq);
            cp16(fsb + (FS_KL + r * KSTu + cq) * 4, Kgl + (size_t)r * 32 + cq);
        }
        // V tile 64 pair-rows x 64 cols via cp.async
        const uint32_t* Vgh = g_Vh + (bh * (Tn / 2) + kt0 / 2) * 64;
        const uint32_t* Vgl = g_Vl + (bh * (Tn / 2) + kt0 / 2) * 64;
        #pragma unroll
        for (int i = 0; i < 8; i++) {
            int lin = tid + i * 128;
            int p = lin >> 4, c = (lin & 15) * 4;
            cp16(fsb + (FS_VH + p * VSTu + c) * 4, Vgh + (size_t)p * 64 + c);
            cp16(fsb + (FS_VL + p * VSTu + c) * 4, Vgl + (size_t)p * 64 + c);
        }
        Ms[tid] = mask[b * Tn + kt0 + tid];
        CP_COMMIT();
        CP_WAIT0();
        __syncthreads();

        #pragma unroll
        for (int half = 0; half < 2; half++) {
            // ---- S = Q @ K^T over 64-key subtile : 3xBF16, term-outer ----
            float sc[8][4];
            #pragma unroll
            for (int n = 0; n < 8; n++)
                #pragma unroll
                for (int c = 0; c < 4; c++) sc[n][c] = 0.0f;
            #pragma unroll
            for (int kk = 0; kk < 4; kk++) {
                uint32_t kbh[8][2], kbl[8][2];
                #pragma unroll
                for (int n = 0; n < 8; n++) {
                    int base = ((half * 8 + n) * 8 + gid) * KSTu + kk * 8 + tig;
                    kbh[n][0] = Kh[base]; kbh[n][1] = Kh[base + 4];
                    kbl[n][0] = Kl[base]; kbl[n][1] = Kl[base + 4];
                }
                #pragma unroll
                for (int n = 0; n < 8; n++) mma16(sc[n], ql[kk], kbh[n]);
                #pragma unroll
                for (int n = 0; n < 8; n++) mma16(sc[n], qh[kk], kbl[n]);
                #pragma unroll
                for (int n = 0; n < 8; n++) mma16(sc[n], qh[kk], kbh[n]);
            }

            // ---- masked scale + faithful zero->-inf quirk + row max ----
            float mx0 = -CUDART_INF_F, mx1 = -CUDART_INF_F;
            #pragma unroll
            for (int n = 0; n < 8; n++) {
                float mk0 = Ms[half * 64 + n * 8 + tig * 2];
                float mk1 = Ms[half * 64 + n * 8 + tig * 2 + 1];
                float s0 = sc[n][0] * inv_dk * mk0; s0 = (s0 == 0.0f) ? -CUDART_INF_F : s0;
                float s1 = sc[n][1] * inv_dk * mk1; s1 = (s1 == 0.0f) ? -CUDART_INF_F : s1;
                float s2 = sc[n][2] * inv_dk * mk0; s2 = (s2 == 0.0f) ? -CUDART_INF_F : s2;
                float s3 = sc[n][3] * inv_dk * mk1; s3 = (s3 == 0.0f) ? -CUDART_INF_F : s3;
                sc[n][0] = s0; sc[n][1] = s1; sc[n][2] = s2; sc[n][3] = s3;
                mx0 = fmaxf(mx0, fmaxf(s0, s1));
                mx1 = fmaxf(mx1, fmaxf(s2, s3));
            }
            mx0 = fmaxf(mx0, __shfl_xor_sync(0xffffffffu, mx0, 1));
            mx0 = fmaxf(mx0, __shfl_xor_sync(0xffffffffu, mx0, 2));
            mx1 = fmaxf(mx1, __shfl_xor_sync(0xffffffffu, mx1, 1));
            mx1 = fmaxf(mx1, __shfl_xor_sync(0xffffffffu, mx1, 2));

            float mn0 = fmaxf(m0, mx0);
            float mn1 = fmaxf(m1, mx1);
            float scale0 = (m0 >= mn0) ? 1.0f : __expf(m0 - mn0);
            float scale1 = (m1 >= mn1) ? 1.0f : __expf(m1 - mn1);

            // ---- exp (in place) + l accumulate ----
            float ls0 = 0.0f, ls1 = 0.0f;
            #pragma unroll
            for (int n = 0; n < 8; n++) {
                float p0 = __expf(sc[n][0] - mn0);
                float p1 = __expf(sc[n][1] - mn0);
                float p2 = __expf(sc[n][2] - mn1);
                float p3 = __expf(sc[n][3] - mn1);
                ls0 += p0 + p1;
                ls1 += p2 + p3;
                sc[n][0] = p0; sc[n][1] = p1; sc[n][2] = p2; sc[n][3] = p3;
            }
            l0 = l0 * scale0 + ls0;
            l1 = l1 * scale1 + ls1;
            m0 = mn0; m1 = mn1;

            // ---- rescale O, then O += P @ V (3-term bf16, term-outer) ----
            #pragma unroll
            for (int n = 0; n < 8; n++) {
                o[n][0] *= scale0; o[n][1] *= scale0;
                o[n][2] *= scale1; o[n][3] *= scale1;
            }
            #pragma unroll
            for (int kk = 0; kk < 4; kk++) {
                uint32_t pah[4], pal[4];
                bf16_split2(sc[2*kk][0],   sc[2*kk][1],   pah[0], pal[0]);
                bf16_split2(sc[2*kk][2],   sc[2*kk][3],   pah[1], pal[1]);
                bf16_split2(sc[2*kk+1][0], sc[2*kk+1][1], pah[2], pal[2]);
                bf16_split2(sc[2*kk+1][2], sc[2*kk+1][3], pah[3], pal[3]);
                uint32_t vbh[8][2], vbl[8][2];
                #pragma unroll
                for (int n = 0; n < 8; n++) {
                    int v0 = (half * 32 + kk * 8 + tig) * VSTu + n * 8 + gid;
                    int v1 = (half * 32 + kk * 8 + 4 + tig) * VSTu + n * 8 + gid;
                    vbh[n][0] = Vh[v0]; vbh[n][1] = Vh[v1];
                    vbl[n][0] = Vl[v0]; vbl[n][1] = Vl[v1];
                }
                #pragma unroll
                for (int n = 0; n < 8; n++) mma16(o[n], pal, vbh[n]);
                #pragma unroll
                for (int n = 0; n < 8; n++) mma16(o[n], pah, vbl[n]);
                #pragma unroll
                for (int n = 0; n < 8; n++) mma16(o[n], pah, vbh[n]);
            }
        }
    }

    // ---- finalize: row sums, normalize, write ctx PRE-SPLIT ----
    l0 += __shfl_xor_sync(0xffffffffu, l0, 1);
    l0 += __shfl_xor_sync(0xffffffffu, l0, 2);
    l1 += __shfl_xor_sync(0xffffffffu, l1, 1);
    l1 += __shfl_xor_sync(0xffffffffu, l1, 2);
    const float i0 = 1.0f / l0;
    const float i1 = 1.0f / l1;

    size_t base0 = (size_t)(b * Tn + qr + gid) * 512 + h * 32;
    size_t base1 = base0 + 8 * 512;
    #pragma unroll
    for (int n = 0; n < 8; n++) {
        int pi = n * 4 + tig;
        uint32_t hh, ll;
        bf16_split2(o[n][0] * i0, o[n][1] * i0, hh, ll);
        g_ctxh[base0 + pi] = hh; g_ctxl[base0 + pi] = ll;
        bf16_split2(o[n][2] * i1, o[n][3] * i1, hh, ll);
        g_ctxh[base1 + pi] = hh; g_ctxl[base1 + pi] = ll;
    }
}

// ---------------------------------------------------------------------------
extern "C" void kernel_launch(void* const* d_in, const int* in_sizes, int n_in,
                              void* d_out, int out_size)
{
    const float* xq   = (const float*)d_in[0];
    const float* xk   = (const float*)d_in[1];
    const float* xv   = (const float*)d_in[2];
    const float* mask = (const float*)d_in[3];
    const float* w_q  = (const float*)d_in[4];
    const float* w_k  = (const float*)d_in[5];
    const float* w_v  = (const float*)d_in[6];
    const float* w_o  = (const float*)d_in[7];
    const float* b_o  = (const float*)d_in[8];
    float* out        = (float*)d_out;

    const int gemm_smem  = GS_BYTES;                          // 59392 B
    const int flash_smem = FS_TOT * (int)sizeof(uint32_t);    // 74240 B
    cudaFuncSetAttribute(proj_kernel,
                         cudaFuncAttributeMaxDynamicSharedMemorySize, gemm_smem);
    cudaFuncSetAttribute(out_proj_kernel,
                         cudaFuncAttributeMaxDynamicSharedMemorySize, gemm_smem);
    cudaFuncSetAttribute(flash_kernel,
                         cudaFuncAttributeMaxDynamicSharedMemorySize, flash_smem);

    // pre-split passes
    split_x_kernel<<<dim3(BTn * DMn / 4 / 256, 1, 3), 256>>>(xq, xk, xv);
    split_w_kernel<<<dim3(Hn * 512 * 64 / 256, 1, 3), 256>>>(w_q, w_k, w_v);
    split_wo_kernel<<<512 * 1024 / 256, 256>>>(w_o);

    dim3 projGrid(BTn / 128, Hn, 3);
    proj_kernel<<<projGrid, 256, gemm_smem>>>();

    split_v_kernel<<<(Bn * Hn * Tn / 2) * 64 / 256, 256>>>();

    dim3 flashGrid(Tn / 64, Hn, Bn);
    flash_kernel<<<flashGrid, 128, flash_smem>>>(mask);

    dim3 outGrid(BTn / 128, DMn / 64);
    out_proj_kernel<<<outGrid, 256, gemm_smem>>>(b_o, out);
}

// round 17
// speedup vs baseline: 1.2248x; 1.0661x over previous
#include <cuda_runtime.h>
#include <cuda_bf16.h>
#include <cuda_fp16.h>
#include <math_constants.h>
#include <cstdint>

#define Bn 2
#define Tn 2048
#define DMn 1024
#define Hn 16
#define DKn 64
#define DVn 64
#define BTn (Bn * Tn)

// ===========================================================================
// Scratch (allocation-free rule: __device__ globals). Q/K/x/w/ctx hold packed
// bf16x2 hi/lo pairs; V holds packed fp16x2 hi/lo pairs (key-pairs).
// ===========================================================================
__device__ uint32_t g_xh[3 * BTn * 512];          // x k-pairs (adjacent cols)
__device__ uint32_t g_xl[3 * BTn * 512];
__device__ uint32_t g_wh[3 * Hn * 512 * 64];      // w_{q,k,v} pairs along DM
__device__ uint32_t g_wl[3 * Hn * 512 * 64];
__device__ uint32_t g_woh[512 * 1024];            // w_o pairs along H*DV
__device__ uint32_t g_wol[512 * 1024];
__device__ uint32_t g_Qh[Bn * Hn * Tn * 32];      // Q dk-pairs (bf16)
__device__ uint32_t g_Ql[Bn * Hn * Tn * 32];
__device__ uint32_t g_Kh[Bn * Hn * Tn * 32];      // K dk-pairs (bf16)
__device__ uint32_t g_Kl[Bn * Hn * Tn * 32];
__device__ float    g_V [Bn * Hn * Tn * DVn];     // V fp32 (pre-repack)
__device__ uint32_t g_Vh[Bn * Hn * (Tn / 2) * 64];// V key-pairs (fp16 hi)
__device__ uint32_t g_Vl[Bn * Hn * (Tn / 2) * 64];// V key-pairs (fp16 lo)
__device__ uint32_t g_ctxh[BTn * 512];            // ctx k-pairs (bf16)
__device__ uint32_t g_ctxl[BTn * 512];

// ===========================================================================
// bf16 / fp16 / cp.async helpers (base PTX, compute_103-safe)
// ===========================================================================
__device__ __forceinline__ uint32_t pack_bf16(float e, float o) {
    __nv_bfloat162 t = __floats2bfloat162_rn(e, o);
    return *(uint32_t*)&t;
}
__device__ __forceinline__ void bf16_split2(float e, float o,
                                            uint32_t& hi, uint32_t& lo) {
    float eh = __bfloat162float(__float2bfloat16_rn(e));
    float oh = __bfloat162float(__float2bfloat16_rn(o));
    hi = pack_bf16(eh, oh);
    lo = pack_bf16(e - eh, o - oh);
}
__device__ __forceinline__ uint32_t pack_f16(float e, float o) {
    __half2 t = __floats2half2_rn(e, o);
    return *(uint32_t*)&t;
}
__device__ __forceinline__ void f16_split2(float e, float o,
                                           uint32_t& hi, uint32_t& lo) {
    float eh = __half2float(__float2half_rn(e));
    float oh = __half2float(__float2half_rn(o));
    hi = pack_f16(eh, oh);
    lo = pack_f16(e - eh, o - oh);
}
// D += A*B, bf16 operands
__device__ __forceinline__ void mma16(float* d, const uint32_t* a, const uint32_t* b) {
    asm volatile(
        "mma.sync.aligned.m16n8k16.row.col.f32.bf16.bf16.f32 "
        "{%0,%1,%2,%3}, {%4,%5,%6,%7}, {%8,%9}, {%0,%1,%2,%3};"
        : "+f"(d[0]), "+f"(d[1]), "+f"(d[2]), "+f"(d[3])
        : "r"(a[0]), "r"(a[1]), "r"(a[2]), "r"(a[3]), "r"(b[0]), "r"(b[1]));
}
// D += A*B, fp16 operands
__device__ __forceinline__ void mma16f(float* d, const uint32_t* a, const uint32_t* b) {
    asm volatile(
        "mma.sync.aligned.m16n8k16.row.col.f32.f16.f16.f32 "
        "{%0,%1,%2,%3}, {%4,%5,%6,%7}, {%8,%9}, {%0,%1,%2,%3};"
        : "+f"(d[0]), "+f"(d[1]), "+f"(d[2]), "+f"(d[3])
        : "r"(a[0]), "r"(a[1]), "r"(a[2]), "r"(a[3]), "r"(b[0]), "r"(b[1]));
}
__device__ __forceinline__ void cp16(uint32_t dst_smem, const void* src) {
    asm volatile("cp.async.cg.shared.global [%0], [%1], 16;"
                 :: "r"(dst_smem), "l"(src));
}
#define CP_COMMIT() asm volatile("cp.async.commit_group;" ::: "memory")
#define CP_WAIT0()  asm volatile("cp.async.wait_group 0;" ::: "memory")
#define CP_WAIT1()  asm volatile("cp.async.wait_group 1;" ::: "memory")

// ===========================================================================
// Pre-split passes
// ===========================================================================
__global__ __launch_bounds__(256) void split_x_kernel(
    const float* __restrict__ xq, const float* __restrict__ xk,
    const float* __restrict__ xv)
{
    const int which = blockIdx.z;
    const float* src = which == 0 ? xq : (which == 1 ? xk : xv);
    uint32_t* dh = g_xh + (size_t)which * BTn * 512;
    uint32_t* dl = g_xl + (size_t)which * BTn * 512;
    int i = blockIdx.x * 256 + threadIdx.x;       // < BTn*DMn/4 = 1048576
    float4 v = ((const float4*)src)[i];
    uint32_t h0, l0, h1, l1;
    bf16_split2(v.x, v.y, h0, l0);
    bf16_split2(v.z, v.w, h1, l1);
    *(uint2*)(dh + 2 * (size_t)i) = make_uint2(h0, h1);
    *(uint2*)(dl + 2 * (size_t)i) = make_uint2(l0, l1);
}
__global__ __launch_bounds__(256) void split_w_kernel(
    const float* __restrict__ wq, const float* __restrict__ wk,
    const float* __restrict__ wv)
{
    const int which = blockIdx.z;
    const float* src = which == 0 ? wq : (which == 1 ? wk : wv);
    uint32_t* dh = g_wh + (size_t)which * Hn * 512 * 64;
    uint32_t* dl = g_wl + (size_t)which * Hn * 512 * 64;
    int idx = blockIdx.x * 256 + threadIdx.x;     // < 524288
    int p = idx >> 6, c = idx & 63;
    float a = src[(size_t)(2 * p) * 64 + c];
    float b = src[(size_t)(2 * p + 1) * 64 + c];
    uint32_t h, l; bf16_split2(a, b, h, l);
    dh[idx] = h; dl[idx] = l;
}
__global__ __launch_bounds__(256) void split_wo_kernel(const float* __restrict__ wo)
{
    int idx = blockIdx.x * 256 + threadIdx.x;     // < 524288
    int p = idx >> 10, c = idx & 1023;
    float a = wo[(size_t)(2 * p) * 1024 + c];
    float b = wo[(size_t)(2 * p + 1) * 1024 + c];
    uint32_t h, l; bf16_split2(a, b, h, l);
    g_woh[idx] = h; g_wol[idx] = l;
}
// V: key-pairs, fp16 hi/lo (PV runs 2-term fp16)
__global__ __launch_bounds__(256) void split_v_kernel()
{
    int idx = blockIdx.x * 256 + threadIdx.x;     // < 2097152
    int p = idx >> 6, c = idx & 63;
    float a = g_V[(size_t)(2 * p) * 64 + c];
    float b = g_V[(size_t)(2 * p + 1) * 64 + c];
    uint32_t h, l; f16_split2(a, b, h, l);
    g_Vh[idx] = h; g_Vl[idx] = l;
}

// ===========================================================================
// 3xBF16 128x64 GEMM body on PRE-SPLIT operands, cp.async DOUBLE-BUFFERED.
// 256 threads = 8 warps (4m x 2n). 32 k-pair tiles of 16.
// ===========================================================================
#define ASTu 20   // A stride in u32 (16 k-pairs + pad)
#define BSTu 72   // B stride in u32 (64 cols + pad)
#define GS_AH 0
#define GS_AL (128 * ASTu)
#define GS_BH (2 * 128 * ASTu)
#define GS_BL (2 * 128 * ASTu + 16 * BSTu)
#define GS_TOT (2 * 128 * ASTu + 2 * 16 * BSTu)   // 7424 u32 per stage
#define GS_BYTES (2 * GS_TOT * 4)                 // 59392 B (two stages)

__device__ __forceinline__ void gemm_body3(
    const uint32_t* __restrict__ Agh, const uint32_t* __restrict__ Agl,
    const uint32_t* __restrict__ Bgh, const uint32_t* __restrict__ Bgl,
    int ldb, float acc[2][4][4], uint32_t* gs)
{
    const int tid  = threadIdx.x;
    const int lane = tid & 31;
    const int wid  = tid >> 5;
    const int gid  = lane >> 2;
    const int tig  = lane & 3;
    const int wm   = (wid >> 1) * 32;
    const int wn   = (wid & 1) * 32;
    const int bkp  = tid >> 4;          // B pair-row 0..15
    const int bc   = (tid & 15) * 4;    // B col

    const uint32_t gsa = (uint32_t)__cvta_generic_to_shared(gs);

    auto issue = [&](int k0p, int stage) {
        uint32_t base = gsa + (uint32_t)stage * GS_TOT * 4;
        #pragma unroll
        for (int i = 0; i < 2; i++) {
            int lin = tid + i * 256;
            int r = lin >> 2, p = (lin & 3) * 4;
            cp16(base + (GS_AH + r * ASTu + p) * 4, Agh + (size_t)r * 512 + k0p + p);
            cp16(base + (GS_AL + r * ASTu + p) * 4, Agl + (size_t)r * 512 + k0p + p);
        }
        cp16(base + (GS_BH + bkp * BSTu + bc) * 4, Bgh + (size_t)(k0p + bkp) * ldb + bc);
        cp16(base + (GS_BL + bkp * BSTu + bc) * 4, Bgl + (size_t)(k0p + bkp) * ldb + bc);
        CP_COMMIT();
    };

    issue(0, 0);

    for (int t = 0; t < 32; t++) {
        const int cur = t & 1;
        if (t < 31) { issue((t + 1) * 16, (t + 1) & 1); CP_WAIT1(); }
        else        { CP_WAIT0(); }
        __syncthreads();

        uint32_t* Ah = gs + cur * GS_TOT + GS_AH;
        uint32_t* Al = gs + cur * GS_TOT + GS_AL;
        uint32_t* Bh = gs + cur * GS_TOT + GS_BH;
        uint32_t* Bl = gs + cur * GS_TOT + GS_BL;

        #pragma unroll
        for (int kk = 0; kk < 2; kk++) {
            uint32_t ah[2][4], al[2][4];
            #pragma unroll
            for (int m = 0; m < 2; m++) {
                int r0 = (wm + m * 16 + gid) * ASTu + kk * 8 + tig;
                int r1 = (wm + m * 16 + 8 + gid) * ASTu + kk * 8 + tig;
                ah[m][0] = Ah[r0]; ah[m][1] = Ah[r1];
                ah[m][2] = Ah[r0 + 4]; ah[m][3] = Ah[r1 + 4];
                al[m][0] = Al[r0]; al[m][1] = Al[r1];
                al[m][2] = Al[r0 + 4]; al[m][3] = Al[r1 + 4];
            }
            uint32_t bh[4][2], bl[4][2];
            #pragma unroll
            for (int n = 0; n < 4; n++) {
                int b0 = (kk * 8 + tig) * BSTu + wn + n * 8 + gid;
                int b1 = (kk * 8 + 4 + tig) * BSTu + wn + n * 8 + gid;
                bh[n][0] = Bh[b0]; bh[n][1] = Bh[b1];
                bl[n][0] = Bl[b0]; bl[n][1] = Bl[b1];
            }
            #pragma unroll
            for (int n = 0; n < 4; n++)
                #pragma unroll
                for (int m = 0; m < 2; m++) mma16(acc[m][n], al[m], bh[n]);
            #pragma unroll
            for (int n = 0; n < 4; n++)
                #pragma unroll
                for (int m = 0; m < 2; m++) mma16(acc[m][n], ah[m], bl[n]);
            #pragma unroll
            for (int n = 0; n < 4; n++)
                #pragma unroll
                for (int m = 0; m < 2; m++) mma16(acc[m][n], ah[m], bh[n]);
        }
        __syncthreads();   // all warps done reading before this stage is refilled
    }
}

// ---------------------------------------------------------------------------
// QKV projection: grid (BT/128, H, 3), block 256, 3 CTAs/SM (reg cap 85).
// ---------------------------------------------------------------------------
__global__ __launch_bounds__(256, 3) void proj_kernel()
{
    extern __shared__ __align__(16) uint32_t gs[];

    const int which = blockIdx.z;
    const int h     = blockIdx.y;
    const int row0  = blockIdx.x * 128;

    const uint32_t* Agh = g_xh + (size_t)which * BTn * 512 + (size_t)row0 * 512;
    const uint32_t* Agl = g_xl + (size_t)which * BTn * 512 + (size_t)row0 * 512;
    const uint32_t* Bgh = g_wh + ((size_t)which * Hn + h) * 512 * 64;
    const uint32_t* Bgl = g_wl + ((size_t)which * Hn + h) * 512 * 64;

    float acc[2][4][4] = {};
    gemm_body3(Agh, Agl, Bgh, Bgl, 64, acc, gs);

    const int lane = threadIdx.x & 31;
    const int wid  = threadIdx.x >> 5;
    const int gid  = lane >> 2;
    const int tig  = lane & 3;
    const int wm   = (wid >> 1) * 32;
    const int wn   = (wid & 1) * 32;

    const int b = row0 >> 11;       // 128-row blocks never straddle batch
    #pragma unroll
    for (int m = 0; m < 2; m++) {
        int r = row0 + wm + m * 16 + gid;
        int t = r & 2047;
        size_t bh = (size_t)(b * Hn + h);
        if (which < 2) {
            uint32_t* oh = (which == 0 ? g_Qh : g_Kh);
            uint32_t* ol = (which == 0 ? g_Ql : g_Kl);
            size_t base0 = (bh * Tn + t) * 32;
            size_t base1 = base0 + 8 * 32;
            #pragma unroll
            for (int n = 0; n < 4; n++) {
                int pi = wn / 2 + n * 4 + tig;
                uint32_t hh, ll;
                bf16_split2(acc[m][n][0], acc[m][n][1], hh, ll);
                oh[base0 + pi] = hh; ol[base0 + pi] = ll;
                bf16_split2(acc[m][n][2], acc[m][n][3], hh, ll);
                oh[base1 + pi] = hh; ol[base1 + pi] = ll;
            }
        } else {
            size_t base0 = (bh * Tn + t) * DVn;
            size_t base1 = base0 + 8 * DVn;
            #pragma unroll
            for (int n = 0; n < 4; n++) {
                int c = wn + n * 8 + tig * 2;
                *(float2*)(g_V + base0 + c) = make_float2(acc[m][n][0], acc[m][n][1]);
                *(float2*)(g_V + base1 + c) = make_float2(acc[m][n][2], acc[m][n][3]);
            }
        }
    }
}

// ---------------------------------------------------------------------------
// Output projection: grid (BT/128, DM/64), block 256, 3 CTAs/SM.
// ---------------------------------------------------------------------------
__global__ __launch_bounds__(256, 3) void out_proj_kernel(
    const float* __restrict__ bo, float* __restrict__ out)
{
    extern __shared__ __align__(16) uint32_t gs[];

    const int row0 = blockIdx.x * 128;
    const int col0 = blockIdx.y * 64;

    float acc[2][4][4] = {};
    gemm_body3(g_ctxh + (size_t)row0 * 512, g_ctxl + (size_t)row0 * 512,
               g_woh + col0, g_wol + col0, 1024, acc, gs);

    const int lane = threadIdx.x & 31;
    const int wid  = threadIdx.x >> 5;
    const int gid  = lane >> 2;
    const int tig  = lane & 3;
    const int wm   = (wid >> 1) * 32;
    const int wn   = (wid & 1) * 32;

    #pragma unroll
    for (int m = 0; m < 2; m++) {
        int r = row0 + wm + m * 16 + gid;
        #pragma unroll
        for (int n = 0; n < 4; n++) {
            int c = col0 + wn + n * 8 + tig * 2;
            float2 bb = *(const float2*)(bo + c);
            *(float2*)(out + (size_t)r * DMn + c) =
                make_float2(acc[m][n][0] + bb.x, acc[m][n][1] + bb.y);
            *(float2*)(out + (size_t)(r + 8) * DMn + c) =
                make_float2(acc[m][n][2] + bb.x, acc[m][n][3] + bb.y);
        }
    }
}

// ---------------------------------------------------------------------------
// Flash attention. QK = 3xBF16 (error is absolute-in-logit -> needs 3 terms).
// PV = 2-term fp16: P single fp16 (rel 2^-11), V = fp16 hi+lo (exact 2^-21).
// grid (T/64, H, B), block 128 (4 warps); warp owns 16 query rows.
// ---------------------------------------------------------------------------
#define KSTu 36
#define VSTu 72
#define FS_KH 0
#define FS_KL (128 * KSTu)
#define FS_VH (2 * 128 * KSTu)
#define FS_VL (FS_VH + 64 * VSTu)
#define FS_M  (FS_VL + 64 * VSTu)
#define FS_TOT (FS_M + 128)               // 18560 u32 = 74240 B

__global__ __launch_bounds__(128, 3) void flash_kernel(
    const float* __restrict__ mask)
{
    extern __shared__ __align__(16) uint32_t fsu[];
    uint32_t* Kh = fsu + FS_KH;
    uint32_t* Kl = fsu + FS_KL;
    uint32_t* Vh = fsu + FS_VH;
    uint32_t* Vl = fsu + FS_VL;
    float*    Ms = (float*)(fsu + FS_M);
    const uint32_t fsb = (uint32_t)__cvta_generic_to_shared(fsu);

    const int tid  = threadIdx.x;
    const int lane = tid & 31;
    const int wid  = tid >> 5;
    const int gid  = lane >> 2;
    const int tig  = lane & 3;

    const int b  = blockIdx.z;
    const int h  = blockIdx.y;
    const int q0 = blockIdx.x * 64;
    const size_t bh = (size_t)(b * Hn + h);
    const int qr = q0 + wid * 16;

    // Q fragments: direct u32 loads from pre-split arrays
    const uint32_t* Qhp = g_Qh + (bh * Tn + qr) * 32;
    const uint32_t* Qlp = g_Ql + (bh * Tn + qr) * 32;
    uint32_t qh[4][4], ql[4][4];
    #pragma unroll
    for (int kk = 0; kk < 4; kk++) {
        qh[kk][0] = Qhp[gid * 32 + kk * 8 + tig];
        qh[kk][1] = Qhp[(gid + 8) * 32 + kk * 8 + tig];
        qh[kk][2] = Qhp[gid * 32 + kk * 8 + 4 + tig];
        qh[kk][3] = Qhp[(gid + 8) * 32 + kk * 8 + 4 + tig];
        ql[kk][0] = Qlp[gid * 32 + kk * 8 + tig];
        ql[kk][1] = Qlp[(gid + 8) * 32 + kk * 8 + tig];
        ql[kk][2] = Qlp[gid * 32 + kk * 8 + 4 + tig];
        ql[kk][3] = Qlp[(gid + 8) * 32 + kk * 8 + 4 + tig];
    }

    float o[8][4];
    #pragma unroll
    for (int n = 0; n < 8; n++)
        #pragma unroll
        for (int c = 0; c < 4; c++) o[n][c] = 0.0f;

    float m0 = -CUDART_INF_F, m1 = -CUDART_INF_F;
    float l0 = 0.0f, l1 = 0.0f;
    const float inv_dk = 1.0f / 64.0f;

    for (int kt0 = 0; kt0 < Tn; kt0 += 128) {
        __syncthreads();   // K/V tiles free for reuse
        // K tile 128 rows x 32 pairs via cp.async
        const uint32_t* Kgh = g_Kh + (bh * Tn + kt0) * 32;
        const uint32_t* Kgl = g_Kl + (bh * Tn + kt0) * 32;
        #pragma unroll
        for (int i = 0; i < 8; i++) {
            int lin = tid + i * 128;
            int r = lin >> 3, cq = (lin & 7) * 4;
            cp16(fsb + (FS_KH + r * KSTu + cq) * 4, Kgh + (size_t)r * 32 + cq);
            cp16(fsb + (FS_KL + r * KSTu + cq) * 4, Kgl + (size_t)r * 32 + cq);
        }
        // V tile 64 pair-rows x 64 cols via cp.async (fp16 hi/lo)
        const uint32_t* Vgh = g_Vh + (bh * (Tn / 2) + kt0 / 2) * 64;
        const uint32_t* Vgl = g_Vl + (bh * (Tn / 2) + kt0 / 2) * 64;
        #pragma unroll
        for (int i = 0; i < 8; i++) {
            int lin = tid + i * 128;
            int p = lin >> 4, c = (lin & 15) * 4;
            cp16(fsb + (FS_VH + p * VSTu + c) * 4, Vgh + (size_t)p * 64 + c);
            cp16(fsb + (FS_VL + p * VSTu + c) * 4, Vgl + (size_t)p * 64 + c);
        }
        Ms[tid] = mask[b * Tn + kt0 + tid];
        CP_COMMIT();
        CP_WAIT0();
        __syncthreads();

        #pragma unroll
        for (int half = 0; half < 2; half++) {
            // ---- S = Q @ K^T over 64-key subtile : 3xBF16, term-outer ----
            float sc[8][4];
            #pragma unroll
            for (int n = 0; n < 8; n++)
                #pragma unroll
                for (int c = 0; c < 4; c++) sc[n][c] = 0.0f;
            #pragma unroll
            for (int kk = 0; kk < 4; kk++) {
                uint32_t kbh[8][2], kbl[8][2];
                #pragma unroll
                for (int n = 0; n < 8; n++) {
                    int base = ((half * 8 + n) * 8 + gid) * KSTu + kk * 8 + tig;
                    kbh[n][0] = Kh[base]; kbh[n][1] = Kh[base + 4];
                    kbl[n][0] = Kl[base]; kbl[n][1] = Kl[base + 4];
                }
                #pragma unroll
                for (int n = 0; n < 8; n++) mma16(sc[n], ql[kk], kbh[n]);
                #pragma unroll
                for (int n = 0; n < 8; n++) mma16(sc[n], qh[kk], kbl[n]);
                #pragma unroll
                for (int n = 0; n < 8; n++) mma16(sc[n], qh[kk], kbh[n]);
            }

            // ---- masked scale + faithful zero->-inf quirk + row max ----
            float mx0 = -CUDART_INF_F, mx1 = -CUDART_INF_F;
            #pragma unroll
            for (int n = 0; n < 8; n++) {
                float mk0 = Ms[half * 64 + n * 8 + tig * 2];
                float mk1 = Ms[half * 64 + n * 8 + tig * 2 + 1];
                float s0 = sc[n][0] * inv_dk * mk0; s0 = (s0 == 0.0f) ? -CUDART_INF_F : s0;
                float s1 = sc[n][1] * inv_dk * mk1; s1 = (s1 == 0.0f) ? -CUDART_INF_F : s1;
                float s2 = sc[n][2] * inv_dk * mk0; s2 = (s2 == 0.0f) ? -CUDART_INF_F : s2;
                float s3 = sc[n][3] * inv_dk * mk1; s3 = (s3 == 0.0f) ? -CUDART_INF_F : s3;
                sc[n][0] = s0; sc[n][1] = s1; sc[n][2] = s2; sc[n][3] = s3;
                mx0 = fmaxf(mx0, fmaxf(s0, s1));
                mx1 = fmaxf(mx1, fmaxf(s2, s3));
            }
            mx0 = fmaxf(mx0, __shfl_xor_sync(0xffffffffu, mx0, 1));
            mx0 = fmaxf(mx0, __shfl_xor_sync(0xffffffffu, mx0, 2));
            mx1 = fmaxf(mx1, __shfl_xor_sync(0xffffffffu, mx1, 1));
            mx1 = fmaxf(mx1, __shfl_xor_sync(0xffffffffu, mx1, 2));

            float mn0 = fmaxf(m0, mx0);
            float mn1 = fmaxf(m1, mx1);
            float scale0 = (m0 >= mn0) ? 1.0f : __expf(m0 - mn0);
            float scale1 = (m1 >= mn1) ? 1.0f : __expf(m1 - mn1);

            // ---- exp (in place) + l accumulate ----
            float ls0 = 0.0f, ls1 = 0.0f;
            #pragma unroll
            for (int n = 0; n < 8; n++) {
                float p0 = __expf(sc[n][0] - mn0);
                float p1 = __expf(sc[n][1] - mn0);
                float p2 = __expf(sc[n][2] - mn1);
                float p3 = __expf(sc[n][3] - mn1);
                ls0 += p0 + p1;
                ls1 += p2 + p3;
                sc[n][0] = p0; sc[n][1] = p1; sc[n][2] = p2; sc[n][3] = p3;
            }
            l0 = l0 * scale0 + ls0;
            l1 = l1 * scale1 + ls1;
            m0 = mn0; m1 = mn1;

            // ---- rescale O, then O += P @ V (2-term fp16: ph*vh + ph*vl) ----
            #pragma unroll
            for (int n = 0; n < 8; n++) {
                o[n][0] *= scale0; o[n][1] *= scale0;
                o[n][2] *= scale1; o[n][3] *= scale1;
            }
            #pragma unroll
            for (int kk = 0; kk < 4; kk++) {
                // A-fragment (fp16) for keys kk*16..+15 directly from S C-frag
                uint32_t pa[4];
                pa[0] = pack_f16(sc[2*kk][0],   sc[2*kk][1]);
                pa[1] = pack_f16(sc[2*kk][2],   sc[2*kk][3]);
                pa[2] = pack_f16(sc[2*kk+1][0], sc[2*kk+1][1]);
                pa[3] = pack_f16(sc[2*kk+1][2], sc[2*kk+1][3]);
                uint32_t vbh[8][2], vbl[8][2];
                #pragma unroll
                for (int n = 0; n < 8; n++) {
                    int v0 = (half * 32 + kk * 8 + tig) * VSTu + n * 8 + gid;
                    int v1 = (half * 32 + kk * 8 + 4 + tig) * VSTu + n * 8 + gid;
                    vbh[n][0] = Vh[v0]; vbh[n][1] = Vh[v1];
                    vbl[n][0] = Vl[v0]; vbl[n][1] = Vl[v1];
                }
                #pragma unroll
                for (int n = 0; n < 8; n++) mma16f(o[n], pa, vbh[n]);
                #pragma unroll
                for (int n = 0; n < 8; n++) mma16f(o[n], pa, vbl[n]);
            }
        }
    }

    // ---- finalize: row sums, normalize, write ctx PRE-SPLIT ----
    l0 += __shfl_xor_sync(0xffffffffu, l0, 1);
    l0 += __shfl_xor_sync(0xffffffffu, l0, 2);
    l1 += __shfl_xor_sync(0xffffffffu, l1, 1);
    l1 += __shfl_xor_sync(0xffffffffu, l1, 2);
    const float i0 = 1.0f / l0;
    const float i1 = 1.0f / l1;

    size_t base0 = (size_t)(b * Tn + qr + gid) * 512 + h * 32;
    size_t base1 = base0 + 8 * 512;
    #pragma unroll
    for (int n = 0; n < 8; n++) {
        int pi = n * 4 + tig;
        uint32_t hh, ll;
        bf16_split2(o[n][0] * i0, o[n][1] * i0, hh, ll);
        g_ctxh[base0 + pi] = hh; g_ctxl[base0 + pi] = ll;
        bf16_split2(o[n][2] * i1, o[n][3] * i1, hh, ll);
        g_ctxh[base1 + pi] = hh; g_ctxl[base1 + pi] = ll;
    }
}

// ---------------------------------------------------------------------------
extern "C" void kernel_launch(void* const* d_in, const int* in_sizes, int n_in,
                              void* d_out, int out_size)
{
    const float* xq   = (const float*)d_in[0];
    const float* xk   = (const float*)d_in[1];
    const float* xv   = (const float*)d_in[2];
    const float* mask = (const float*)d_in[3];
    const float* w_q  = (const float*)d_in[4];
    const float* w_k  = (const float*)d_in[5];
    const float* w_v  = (const float*)d_in[6];
    const float* w_o  = (const float*)d_in[7];
    const float* b_o  = (const float*)d_in[8];
    float* out        = (float*)d_out;

    const int gemm_smem  = GS_BYTES;                          // 59392 B
    const int flash_smem = FS_TOT * (int)sizeof(uint32_t);    // 74240 B
    cudaFuncSetAttribute(proj_kernel,
                         cudaFuncAttributeMaxDynamicSharedMemorySize, gemm_smem);
    cudaFuncSetAttribute(out_proj_kernel,
                         cudaFuncAttributeMaxDynamicSharedMemorySize, gemm_smem);
    cudaFuncSetAttribute(flash_kernel,
                         cudaFuncAttributeMaxDynamicSharedMemorySize, flash_smem);

    // pre-split passes
    split_x_kernel<<<dim3(BTn * DMn / 4 / 256, 1, 3), 256>>>(xq, xk, xv);
    split_w_kernel<<<dim3(Hn * 512 * 64 / 256, 1, 3), 256>>>(w_q, w_k, w_v);
    split_wo_kernel<<<512 * 1024 / 256, 256>>>(w_o);

    dim3 projGrid(BTn / 128, Hn, 3);
    proj_kernel<<<projGrid, 256, gemm_smem>>>();

    split_v_kernel<<<(Bn * Hn * Tn / 2) * 64 / 256, 256>>>();

    dim3 flashGrid(Tn / 64, Hn, Bn);
    flash_kernel<<<flashGrid, 128, flash_smem>>>(mask);

    dim3 outGrid(BTn / 128, DMn / 64);
    out_proj_kernel<<<outGrid, 256, gemm_smem>>>(b_o, out);
}